// round 2
// baseline (speedup 1.0000x reference)
#include <cuda_runtime.h>

// BatchedGAT: out[b,i,hf] = (sum_j p_ij * h[b,j,hf]) / (sum_j p_ij) + bias[hf]
//   h = x @ W  (fp32 GEMM, f32x2-packed FMA)
//   p_ij = (adj[b,i,j] > 0.5) ? exp(leaky(e_dst[b,i,h] + e_src[b,j,h])) : 0
// No max-subtraction needed: logits ~ N(0,2), exp stays well inside fp32 range,
// and jax's max-subtraction cancels exactly in the ratio.

#define DEV __device__ __forceinline__
using u64 = unsigned long long;

DEV u64 packff(float lo, float hi) {
    u64 r; asm("mov.b64 %0, {%1,%2};" : "=l"(r) : "f"(lo), "f"(hi)); return r;
}
DEV u64 fma2(u64 a, u64 b, u64 c) {
    u64 r; asm("fma.rn.f32x2 %0, %1, %2, %3;" : "=l"(r) : "l"(a), "l"(b), "l"(c)); return r;
}
DEV float2 unpackff(u64 v) {
    float lo, hi; asm("mov.b64 {%0,%1}, %2;" : "=f"(lo), "=f"(hi) : "l"(v));
    return make_float2(lo, hi);
}

constexpr int Bb = 16;
constexpr int Nn = 1024;
constexpr int Dd = 256;
constexpr int Hh = 4;
constexpr int HF = 256;          // H*F
constexpr int Mrows = Bb * Nn;   // 16384

// Scratch (device globals: no allocations allowed)
__device__ float g_h[Mrows * HF];     // 16.8 MB: h[b,n,hf]
__device__ float g_es[Mrows * Hh];    // e_src[b,n,h]
__device__ float g_ed[Mrows * Hh];    // e_dst[b,n,h]

// ---------------------------------------------------------------------------
// Kernel 1: h = x @ W.   A=[16384,256] row-major, W=[256,256] row-major.
// 128x64 CTA tile, BK=16, 256 threads, per-thread 8(m)x4(n) via f32x2 pairs.
// ---------------------------------------------------------------------------
__global__ __launch_bounds__(256) void gemm_xw(const float* __restrict__ A,
                                               const float* __restrict__ W) {
    __shared__ float As[16][128];   // transposed A tile: As[k][m]
    __shared__ float Bs[16][64];

    const int tid = threadIdx.x;
    const int bm = blockIdx.y;      // 0..127
    const int bn = blockIdx.x;      // 0..3
    const int ty = tid >> 4;        // 0..15  (m direction)
    const int tx = tid & 15;        // 0..15  (n direction)

    u64 acc[16];                    // acc[m2*4+n]: m2 row-pairs, n cols
#pragma unroll
    for (int i = 0; i < 16; ++i) acc[i] = 0ull;

    const float* Ab = A + bm * 128 * Dd;
    const float* Wb = W + bn * 64;

    const int arow = tid >> 2;            // 0..63
    const int acol = (tid & 3) << 2;      // 0,4,8,12
    const int brow = tid >> 4;            // 0..15
    const int bcol = (tid & 15) << 2;     // 0..60

    for (int kt = 0; kt < Dd; kt += 16) {
        float4 a0 = *(const float4*)(Ab + arow * Dd + kt + acol);
        float4 a1 = *(const float4*)(Ab + (arow + 64) * Dd + kt + acol);
        float4 bv = *(const float4*)(Wb + (kt + brow) * HF + bcol);
        __syncthreads();   // previous compute done before overwriting smem
        As[acol + 0][arow] = a0.x; As[acol + 1][arow] = a0.y;
        As[acol + 2][arow] = a0.z; As[acol + 3][arow] = a0.w;
        As[acol + 0][arow + 64] = a1.x; As[acol + 1][arow + 64] = a1.y;
        As[acol + 2][arow + 64] = a1.z; As[acol + 3][arow + 64] = a1.w;
        *(float4*)&Bs[brow][bcol] = bv;
        __syncthreads();

#pragma unroll
        for (int kk = 0; kk < 16; ++kk) {
            // A rows come pre-packed as f32 pairs (adjacent m in transposed tile)
            ulonglong2 a01 = *(const ulonglong2*)&As[kk][ty * 4];
            ulonglong2 a23 = *(const ulonglong2*)&As[kk][64 + ty * 4];
            float4 b = *(const float4*)&Bs[kk][tx * 4];
            u64 av[4] = { a01.x, a01.y, a23.x, a23.y };
            u64 bvp[4] = { packff(b.x, b.x), packff(b.y, b.y),
                           packff(b.z, b.z), packff(b.w, b.w) };
#pragma unroll
            for (int m2 = 0; m2 < 4; ++m2)
#pragma unroll
                for (int n = 0; n < 4; ++n)
                    acc[m2 * 4 + n] = fma2(av[m2], bvp[n], acc[m2 * 4 + n]);
        }
    }

    const int colbase = bn * 64 + tx * 4;
#pragma unroll
    for (int m2 = 0; m2 < 4; ++m2) {
        int r0 = bm * 128 + ((m2 >= 2) ? 64 : 0) + ty * 4 + (m2 & 1) * 2;
        float2 p0 = unpackff(acc[m2 * 4 + 0]);
        float2 p1 = unpackff(acc[m2 * 4 + 1]);
        float2 p2 = unpackff(acc[m2 * 4 + 2]);
        float2 p3 = unpackff(acc[m2 * 4 + 3]);
        float4 row0 = make_float4(p0.x, p1.x, p2.x, p3.x);
        float4 row1 = make_float4(p0.y, p1.y, p2.y, p3.y);
        *(float4*)&g_h[r0 * HF + colbase] = row0;
        *(float4*)&g_h[(r0 + 1) * HF + colbase] = row1;
    }
}

// ---------------------------------------------------------------------------
// Kernel 2: e_src/e_dst[b,n,h] = sum_f h[b,n,h,f] * a[h,f].
// One block per row; thread t owns hf=t; warp-reduce, combine warp pairs.
// ---------------------------------------------------------------------------
__global__ __launch_bounds__(256) void e_kernel(const float* __restrict__ a_src,
                                                const float* __restrict__ a_dst) {
    const int row = blockIdx.x;
    const int t = threadIdx.x;
    float v = g_h[row * HF + t];
    float s = v * a_src[t];
    float d = v * a_dst[t];
#pragma unroll
    for (int o = 16; o > 0; o >>= 1) {
        s += __shfl_down_sync(0xffffffffu, s, o);
        d += __shfl_down_sync(0xffffffffu, d, o);
    }
    __shared__ float ss[8], sd[8];
    const int w = t >> 5;
    if ((t & 31) == 0) { ss[w] = s; sd[w] = d; }
    __syncthreads();
    if (t < Hh) {
        g_es[row * Hh + t] = ss[2 * t] + ss[2 * t + 1];
        g_ed[row * Hh + t] = sd[2 * t] + sd[2 * t + 1];
    }
}

// ---------------------------------------------------------------------------
// Kernel 3: masked softmax + aggregation (flash-style, unnormalized then divide).
// Grid: (N/32, B). CTA: 32 target rows. Warp w owns hf in [32w, 32w+32);
// lane = local target row i. h_sm reads are warp-uniform -> broadcast LDS.128.
// ---------------------------------------------------------------------------
__global__ __launch_bounds__(256) void attn_kernel(const float* __restrict__ adj,
                                                   const float* __restrict__ bias,
                                                   float* __restrict__ out) {
    __shared__ float h_sm[32][256];     // 32 KB
    __shared__ float adj_sm[32][33];    // padded: conflict-free column reads
    __shared__ float es_sm[32][4];

    const int tid = threadIdx.x;
    const int b = blockIdx.y;
    const int i0 = blockIdx.x << 5;
    const int w = tid >> 5;             // warp id 0..7 -> hf block
    const int lane = tid & 31;          // local target row
    const int hh = w >> 1;              // head of this warp's hf block

    const float ed = g_ed[(b * Nn + i0 + lane) * Hh + hh];

    u64 acc[16];
#pragma unroll
    for (int q = 0; q < 16; ++q) acc[q] = 0ull;
    float den = 0.f;

    const int adjr = tid >> 3;
    const int adjc = (tid & 7) << 2;

    for (int jt = 0; jt < 32; ++jt) {
        const int j0 = jt << 5;
        __syncthreads();   // previous tile's compute done before restage
        // h tile: 32 rows x 256 floats, 8 float4 per thread, coalesced
#pragma unroll
        for (int q = 0; q < 8; ++q) {
            int idx = tid + (q << 8);
            int r = idx >> 6, c = (idx & 63) << 2;
            *(float4*)&h_sm[r][c] = *(const float4*)&g_h[(b * Nn + j0 + r) * HF + c];
        }
        // adj tile (scalar STS into padded array)
        {
            float4 av = *(const float4*)&adj[(b * Nn + i0 + adjr) * Nn + j0 + adjc];
            adj_sm[adjr][adjc + 0] = av.x; adj_sm[adjr][adjc + 1] = av.y;
            adj_sm[adjr][adjc + 2] = av.z; adj_sm[adjr][adjc + 3] = av.w;
        }
        if (tid < 128)
            es_sm[tid >> 2][tid & 3] = g_es[(b * Nn + j0 + (tid >> 2)) * Hh + (tid & 3)];
        __syncthreads();

#pragma unroll 4
        for (int j = 0; j < 32; ++j) {
            float es = es_sm[j][hh];                 // broadcast
            float l = ed + es;
            l = fmaxf(l, 0.2f * l);                  // LeakyReLU (slope<1)
            float aj = adj_sm[lane][j];              // per-lane, padded
            float p = (aj > 0.5f) ? __expf(l) : 0.f;
            den += p;
            u64 p2 = packff(p, p);
            const ulonglong2* hp = (const ulonglong2*)&h_sm[j][w << 5];
#pragma unroll
            for (int q = 0; q < 8; ++q) {
                ulonglong2 hv = hp[q];               // uniform addr -> broadcast
                acc[2 * q]     = fma2(p2, hv.x, acc[2 * q]);
                acc[2 * q + 1] = fma2(p2, hv.y, acc[2 * q + 1]);
            }
        }
    }

    const float inv = 1.0f / den;
    float* orow = out + (b * Nn + i0 + lane) * HF + (w << 5);
#pragma unroll
    for (int q = 0; q < 8; ++q) {
        float2 v0 = unpackff(acc[2 * q]);
        float2 v1 = unpackff(acc[2 * q + 1]);
        float4 bz = *(const float4*)&bias[(w << 5) + 4 * q];
        float4 o;
        o.x = v0.x * inv + bz.x;
        o.y = v0.y * inv + bz.y;
        o.z = v1.x * inv + bz.z;
        o.w = v1.y * inv + bz.w;
        *(float4*)&orow[4 * q] = o;
    }
}

// ---------------------------------------------------------------------------
extern "C" void kernel_launch(void* const* d_in, const int* in_sizes, int n_in,
                              void* d_out, int out_size) {
    (void)in_sizes; (void)n_in; (void)out_size;
    const float* x     = (const float*)d_in[0];  // [16,1024,256]
    const float* adj   = (const float*)d_in[1];  // [16,1024,1024]
    const float* W     = (const float*)d_in[2];  // [256,256]
    const float* a_src = (const float*)d_in[3];  // [4,64]
    const float* a_dst = (const float*)d_in[4];  // [4,64]
    const float* bias  = (const float*)d_in[5];  // [256]
    float* out = (float*)d_out;                  // [16,1024,256]

    gemm_xw<<<dim3(HF / 64, Mrows / 128), 256>>>(x, W);
    e_kernel<<<Mrows, 256>>>(a_src, a_dst);
    attn_kernel<<<dim3(Nn / 32, Bb), 256>>>(adj, bias, out);
}

// round 3
// speedup vs baseline: 1.1274x; 1.1274x over previous
#include <cuda_runtime.h>

// BatchedGAT: out[b,i,hf] = (sum_j p_ij * h[b,j,hf]) / (sum_j p_ij) + bias[hf]
//   h = x @ W  (fp32 GEMM, f32x2-packed FMA)
//   p_ij = (adj[b,i,j] > 0.5) ? exp(leaky(e_dst[b,i,h] + e_src[b,j,h])) : 0
// No max-subtraction needed: logits ~ N(0,2), exp stays well inside fp32 range,
// and jax's max-subtraction cancels exactly in the ratio.

#define DEV __device__ __forceinline__
using u64 = unsigned long long;

DEV u64 packff(float lo, float hi) {
    u64 r; asm("mov.b64 %0, {%1,%2};" : "=l"(r) : "f"(lo), "f"(hi)); return r;
}
DEV u64 fma2(u64 a, u64 b, u64 c) {
    u64 r; asm("fma.rn.f32x2 %0, %1, %2, %3;" : "=l"(r) : "l"(a), "l"(b), "l"(c)); return r;
}
DEV float2 unpackff(u64 v) {
    float lo, hi; asm("mov.b64 {%0,%1}, %2;" : "=f"(lo), "=f"(hi) : "l"(v));
    return make_float2(lo, hi);
}

constexpr int Bb = 16;
constexpr int Nn = 1024;
constexpr int Dd = 256;
constexpr int Hh = 4;
constexpr int HF = 256;          // H*F
constexpr int Mrows = Bb * Nn;   // 16384

// Scratch (device globals: no allocations allowed)
__device__ float g_h[Mrows * HF];     // 16.8 MB: h[b,n,hf]
__device__ float g_es[Mrows * Hh];    // e_src[b,n,h]
__device__ float g_ed[Mrows * Hh];    // e_dst[b,n,h]

// ---------------------------------------------------------------------------
// Kernel 1: h = x @ W.   A=[16384,256] row-major, W=[256,256] row-major.
// 128x64 CTA tile, BK=16, 256 threads, per-thread 8(m)x4(n) via f32x2 pairs.
// ---------------------------------------------------------------------------
__global__ __launch_bounds__(256) void gemm_xw(const float* __restrict__ A,
                                               const float* __restrict__ W) {
    __shared__ float As[16][128];   // transposed A tile: As[k][m]
    __shared__ float Bs[16][64];

    const int tid = threadIdx.x;
    const int bm = blockIdx.y;      // 0..127
    const int bn = blockIdx.x;      // 0..3
    const int ty = tid >> 4;        // 0..15  (m direction)
    const int tx = tid & 15;        // 0..15  (n direction)

    u64 acc[16];                    // acc[m2*4+n]: m2 row-pairs, n cols
#pragma unroll
    for (int i = 0; i < 16; ++i) acc[i] = 0ull;

    const float* Ab = A + bm * 128 * Dd;
    const float* Wb = W + bn * 64;

    const int arow = tid >> 2;            // 0..63
    const int acol = (tid & 3) << 2;      // 0,4,8,12
    const int brow = tid >> 4;            // 0..15
    const int bcol = (tid & 15) << 2;     // 0..60

    for (int kt = 0; kt < Dd; kt += 16) {
        float4 a0 = *(const float4*)(Ab + arow * Dd + kt + acol);
        float4 a1 = *(const float4*)(Ab + (arow + 64) * Dd + kt + acol);
        float4 bv = *(const float4*)(Wb + (kt + brow) * HF + bcol);
        __syncthreads();   // previous compute done before overwriting smem
        As[acol + 0][arow] = a0.x; As[acol + 1][arow] = a0.y;
        As[acol + 2][arow] = a0.z; As[acol + 3][arow] = a0.w;
        As[acol + 0][arow + 64] = a1.x; As[acol + 1][arow + 64] = a1.y;
        As[acol + 2][arow + 64] = a1.z; As[acol + 3][arow + 64] = a1.w;
        *(float4*)&Bs[brow][bcol] = bv;
        __syncthreads();

#pragma unroll
        for (int kk = 0; kk < 16; ++kk) {
            // A rows come pre-packed as f32 pairs (adjacent m in transposed tile)
            ulonglong2 a01 = *(const ulonglong2*)&As[kk][ty * 4];
            ulonglong2 a23 = *(const ulonglong2*)&As[kk][64 + ty * 4];
            float4 b = *(const float4*)&Bs[kk][tx * 4];
            u64 av[4] = { a01.x, a01.y, a23.x, a23.y };
            u64 bvp[4] = { packff(b.x, b.x), packff(b.y, b.y),
                           packff(b.z, b.z), packff(b.w, b.w) };
#pragma unroll
            for (int m2 = 0; m2 < 4; ++m2)
#pragma unroll
                for (int n = 0; n < 4; ++n)
                    acc[m2 * 4 + n] = fma2(av[m2], bvp[n], acc[m2 * 4 + n]);
        }
    }

    const int colbase = bn * 64 + tx * 4;
#pragma unroll
    for (int m2 = 0; m2 < 4; ++m2) {
        int r0 = bm * 128 + ((m2 >= 2) ? 64 : 0) + ty * 4 + (m2 & 1) * 2;
        float2 p0 = unpackff(acc[m2 * 4 + 0]);
        float2 p1 = unpackff(acc[m2 * 4 + 1]);
        float2 p2 = unpackff(acc[m2 * 4 + 2]);
        float2 p3 = unpackff(acc[m2 * 4 + 3]);
        float4 row0 = make_float4(p0.x, p1.x, p2.x, p3.x);
        float4 row1 = make_float4(p0.y, p1.y, p2.y, p3.y);
        *(float4*)&g_h[r0 * HF + colbase] = row0;
        *(float4*)&g_h[(r0 + 1) * HF + colbase] = row1;
    }
}

// ---------------------------------------------------------------------------
// Kernel 2: e_src/e_dst[b,n,h] = sum_f h[b,n,h,f] * a[h,f].
// One block per row; thread t owns hf=t; warp-reduce, combine warp pairs.
// ---------------------------------------------------------------------------
__global__ __launch_bounds__(256) void e_kernel(const float* __restrict__ a_src,
                                                const float* __restrict__ a_dst) {
    const int row = blockIdx.x;
    const int t = threadIdx.x;
    float v = g_h[row * HF + t];
    float s = v * a_src[t];
    float d = v * a_dst[t];
#pragma unroll
    for (int o = 16; o > 0; o >>= 1) {
        s += __shfl_down_sync(0xffffffffu, s, o);
        d += __shfl_down_sync(0xffffffffu, d, o);
    }
    __shared__ float ss[8], sd[8];
    const int w = t >> 5;
    if ((t & 31) == 0) { ss[w] = s; sd[w] = d; }
    __syncthreads();
    if (t < Hh) {
        g_es[row * Hh + t] = ss[2 * t] + ss[2 * t + 1];
        g_ed[row * Hh + t] = sd[2 * t] + sd[2 * t + 1];
    }
}

// ---------------------------------------------------------------------------
// Kernel 3: masked softmax + aggregation, two-phase per 32-j tile.
//
// Phase A: each (i,h) logit row computed ONCE (warp w: h=w>>1, i in
//          [(w&1)*16, +16), lane=j). p stored as plain float in smem laid
//          out [h][j][i] (padded to 36) so Phase B reads are float4 and
//          conflict-free. Denominator accumulated via shfl-xor into a
//          per-lane register (lane t owns task t).
//
// Phase B: warp w owns hf [32w, 32w+32) (head w>>1) and ALL 32 i:
//          lane = (li=lane>>2 -> 4 i's, lh=lane&3 -> 8 hf).
//          Per j: 1x LDS.128 p (4 i), 2x LDS.128 h (8 hf), 16x FFMA2.
//          FFMA2-pace-bound by design (issue ratio ~27:16 < 2:1).
// ---------------------------------------------------------------------------
__global__ __launch_bounds__(256) void attn_kernel(const float* __restrict__ adj,
                                                   const float* __restrict__ bias,
                                                   float* __restrict__ out) {
    __shared__ float h_sm[32][256];       // 32 KB
    __shared__ float p2f[4][32][36];      // [h][j][i+pad] 18.4 KB
    __shared__ float den_sm[4][32];
    __shared__ float ed_sm[4][32];

    const int tid = threadIdx.x;
    const int b = blockIdx.y;
    const int i0 = blockIdx.x << 5;
    const int w = tid >> 5;
    const int lane = tid & 31;
    // Phase A mapping
    const int hA = w >> 1;                // head
    const int ibase = (w & 1) << 4;       // 0 or 16
    // Phase B mapping
    const int li = lane >> 2;             // 0..7 -> i group of 4
    const int lh = lane & 3;              // 0..3 -> 8 hf
    const int hfB = w << 5;               // warp's hf base (head hfB/64 == hA)

    if (tid < 128)
        ed_sm[tid >> 5][tid & 31] =
            g_ed[(b * Nn + i0 + (tid & 31)) * Hh + (tid >> 5)];

    u64 acc[16];
#pragma unroll
    for (int q = 0; q < 16; ++q) acc[q] = 0ull;
    float den_reg = 0.f;

    __syncthreads();    // ed_sm ready

    for (int jt = 0; jt < 32; ++jt) {
        const int j0 = jt << 5;

        // Prefetch into registers (no smem hazard before the barrier)
        float4 hbuf[8];
#pragma unroll
        for (int q = 0; q < 8; ++q) {
            int idx = tid + (q << 8);
            int r = idx >> 6, c = (idx & 63) << 2;
            hbuf[q] = *(const float4*)&g_h[(b * Nn + j0 + r) * HF + c];
        }
        float es_r = g_es[(b * Nn + j0 + lane) * Hh + hA];
        float adj_r[16];
#pragma unroll
        for (int t = 0; t < 16; ++t)
            adj_r[t] = adj[(b * Nn + i0 + ibase + t) * Nn + j0 + lane];

        __syncthreads();   // previous Phase B done with h_sm / p2f

#pragma unroll
        for (int q = 0; q < 8; ++q) {
            int idx = tid + (q << 8);
            int r = idx >> 6, c = (idx & 63) << 2;
            *(float4*)&h_sm[r][c] = hbuf[q];
        }

        // ---- Phase A: p + denominator, each (i,h) once ----
#pragma unroll
        for (int t = 0; t < 16; ++t) {
            const int i = ibase + t;
            float l = ed_sm[hA][i] + es_r;
            l = fmaxf(l, 0.2f * l);                    // LeakyReLU
            float p = (adj_r[t] > 0.5f) ? __expf(l) : 0.f;
            p2f[hA][lane][i] = p;                      // lane = j
            float s = p;
#pragma unroll
            for (int o = 16; o > 0; o >>= 1)
                s += __shfl_xor_sync(0xffffffffu, s, o);
            if (lane == t) den_reg += s;               // lane t owns task t
        }

        __syncthreads();   // h_sm + p2f ready

        // ---- Phase B: dense aggregation ----
#pragma unroll 4
        for (int j = 0; j < 32; ++j) {
            float4 pv = *(const float4*)&p2f[hA][j][li << 2];
            const ulonglong2* hp =
                (const ulonglong2*)&h_sm[j][hfB + (lh << 3)];
            ulonglong2 h01 = hp[0];
            ulonglong2 h23 = hp[1];
            u64 pk0 = packff(pv.x, pv.x);
            u64 pk1 = packff(pv.y, pv.y);
            u64 pk2 = packff(pv.z, pv.z);
            u64 pk3 = packff(pv.w, pv.w);
            acc[0]  = fma2(pk0, h01.x, acc[0]);
            acc[1]  = fma2(pk0, h01.y, acc[1]);
            acc[2]  = fma2(pk0, h23.x, acc[2]);
            acc[3]  = fma2(pk0, h23.y, acc[3]);
            acc[4]  = fma2(pk1, h01.x, acc[4]);
            acc[5]  = fma2(pk1, h01.y, acc[5]);
            acc[6]  = fma2(pk1, h23.x, acc[6]);
            acc[7]  = fma2(pk1, h23.y, acc[7]);
            acc[8]  = fma2(pk2, h01.x, acc[8]);
            acc[9]  = fma2(pk2, h01.y, acc[9]);
            acc[10] = fma2(pk2, h23.x, acc[10]);
            acc[11] = fma2(pk2, h23.y, acc[11]);
            acc[12] = fma2(pk3, h01.x, acc[12]);
            acc[13] = fma2(pk3, h01.y, acc[13]);
            acc[14] = fma2(pk3, h23.x, acc[14]);
            acc[15] = fma2(pk3, h23.y, acc[15]);
        }
    }

    // Publish denominators (lane t of Phase-A warp holds task t's den)
    if (lane < 16) den_sm[hA][ibase + lane] = den_reg;
    __syncthreads();

    const float4 bz0 = *(const float4*)&bias[hfB + (lh << 3)];
    const float4 bz1 = *(const float4*)&bias[hfB + (lh << 3) + 4];
#pragma unroll
    for (int k = 0; k < 4; ++k) {
        const int i = (li << 2) + k;
        const float inv = 1.0f / den_sm[hA][i];
        float* orow = out + (b * Nn + i0 + i) * HF + hfB + (lh << 3);
        float2 v0 = unpackff(acc[k * 4 + 0]);
        float2 v1 = unpackff(acc[k * 4 + 1]);
        float2 v2 = unpackff(acc[k * 4 + 2]);
        float2 v3 = unpackff(acc[k * 4 + 3]);
        float4 o0, o1;
        o0.x = v0.x * inv + bz0.x;  o0.y = v0.y * inv + bz0.y;
        o0.z = v1.x * inv + bz0.z;  o0.w = v1.y * inv + bz0.w;
        o1.x = v2.x * inv + bz1.x;  o1.y = v2.y * inv + bz1.y;
        o1.z = v3.x * inv + bz1.z;  o1.w = v3.y * inv + bz1.w;
        *(float4*)&orow[0] = o0;
        *(float4*)&orow[4] = o1;
    }
}

// ---------------------------------------------------------------------------
extern "C" void kernel_launch(void* const* d_in, const int* in_sizes, int n_in,
                              void* d_out, int out_size) {
    (void)in_sizes; (void)n_in; (void)out_size;
    const float* x     = (const float*)d_in[0];  // [16,1024,256]
    const float* adj   = (const float*)d_in[1];  // [16,1024,1024]
    const float* W     = (const float*)d_in[2];  // [256,256]
    const float* a_src = (const float*)d_in[3];  // [4,64]
    const float* a_dst = (const float*)d_in[4];  // [4,64]
    const float* bias  = (const float*)d_in[5];  // [256]
    float* out = (float*)d_out;                  // [16,1024,256]

    gemm_xw<<<dim3(HF / 64, Mrows / 128), 256>>>(x, W);
    e_kernel<<<Mrows, 256>>>(a_src, a_dst);
    attn_kernel<<<dim3(Nn / 32, Bb), 256>>>(adj, bias, out);
}

// round 6
// speedup vs baseline: 2.3610x; 2.0943x over previous
#include <cuda_runtime.h>
#include <cstdint>

// BatchedGAT round 4: legacy tensor-core (mma.sync tf32) flash-style attention.
//   h = x @ W                     (fp32 f32x2 GEMM, unchanged)
//   e_src/e_dst                   (unchanged)
//   pack: g_hTf = B-fragment-ordered tf32 images of h (per bh, per 8-j block)
//   attn: warps compute P fragments in registers (mask+leaky+exp -> tf32),
//         mma.sync.m16n8k8 accumulates D[i,f] in fp32; den exact fp32.
// NOTE: tcgen05/TMEM is 'a'-gated and the harness PTX target is plain sm_103,
// so the tensor path must use baseline mma.sync (HMMA).

#define DEV __device__ __forceinline__
using u64 = unsigned long long;
using u32 = unsigned int;

DEV u64 packff(float lo, float hi) {
    u64 r; asm("mov.b64 %0, {%1,%2};" : "=l"(r) : "f"(lo), "f"(hi)); return r;
}
DEV u64 fma2(u64 a, u64 b, u64 c) {
    u64 r; asm("fma.rn.f32x2 %0, %1, %2, %3;" : "=l"(r) : "l"(a), "l"(b), "l"(c)); return r;
}
DEV float2 unpackff(u64 v) {
    float lo, hi; asm("mov.b64 {%0,%1}, %2;" : "=f"(lo), "=f"(hi) : "l"(v));
    return make_float2(lo, hi);
}
DEV u32 cvt_tf32(float x) {
    u32 r; asm("cvt.rna.tf32.f32 %0, %1;" : "=r"(r) : "f"(x)); return r;
}
DEV void mma16n8k8(float* c, u32 a0, u32 a1, u32 a2, u32 a3, u32 b0, u32 b1) {
    asm volatile(
        "mma.sync.aligned.m16n8k8.row.col.f32.tf32.tf32.f32 "
        "{%0,%1,%2,%3}, {%4,%5,%6,%7}, {%8,%9}, {%0,%1,%2,%3};"
        : "+f"(c[0]), "+f"(c[1]), "+f"(c[2]), "+f"(c[3])
        : "r"(a0), "r"(a1), "r"(a2), "r"(a3), "r"(b0), "r"(b1));
}

constexpr int Bb = 16, Nn = 1024, Dd = 256, Hh = 4, HF = 256;
constexpr int Mrows = Bb * Nn;

__device__ float g_h[Mrows * HF];            // h[b,n,hf]
__device__ float g_es[Mrows * Hh];
__device__ float g_ed[Mrows * Hh];
// B fragments: [bh][jb(128)][n(8)][lane(32)] -> uint2 (b0=j0+lane%4, b1=+4), tf32
__device__ uint2 g_hTf[64 * 128 * 8 * 32];   // 16.8 MB

// ---------------------------------------------------------------------------
// Kernel 1: h = x @ W (unchanged, known-good)
// ---------------------------------------------------------------------------
__global__ __launch_bounds__(256) void gemm_xw(const float* __restrict__ A,
                                               const float* __restrict__ W) {
    __shared__ float As[16][128];
    __shared__ float Bs[16][64];
    const int tid = threadIdx.x;
    const int bm = blockIdx.y, bn = blockIdx.x;
    const int ty = tid >> 4, tx = tid & 15;

    u64 acc[16];
#pragma unroll
    for (int i = 0; i < 16; ++i) acc[i] = 0ull;

    const float* Ab = A + bm * 128 * Dd;
    const float* Wb = W + bn * 64;
    const int arow = tid >> 2, acol = (tid & 3) << 2;
    const int brow = tid >> 4, bcol = (tid & 15) << 2;

    for (int kt = 0; kt < Dd; kt += 16) {
        float4 a0 = *(const float4*)(Ab + arow * Dd + kt + acol);
        float4 a1 = *(const float4*)(Ab + (arow + 64) * Dd + kt + acol);
        float4 bv = *(const float4*)(Wb + (kt + brow) * HF + bcol);
        __syncthreads();
        As[acol + 0][arow] = a0.x; As[acol + 1][arow] = a0.y;
        As[acol + 2][arow] = a0.z; As[acol + 3][arow] = a0.w;
        As[acol + 0][arow + 64] = a1.x; As[acol + 1][arow + 64] = a1.y;
        As[acol + 2][arow + 64] = a1.z; As[acol + 3][arow + 64] = a1.w;
        *(float4*)&Bs[brow][bcol] = bv;
        __syncthreads();
#pragma unroll
        for (int kk = 0; kk < 16; ++kk) {
            ulonglong2 a01 = *(const ulonglong2*)&As[kk][ty * 4];
            ulonglong2 a23 = *(const ulonglong2*)&As[kk][64 + ty * 4];
            float4 b = *(const float4*)&Bs[kk][tx * 4];
            u64 av[4] = { a01.x, a01.y, a23.x, a23.y };
            u64 bp[4] = { packff(b.x, b.x), packff(b.y, b.y),
                          packff(b.z, b.z), packff(b.w, b.w) };
#pragma unroll
            for (int m2 = 0; m2 < 4; ++m2)
#pragma unroll
                for (int n = 0; n < 4; ++n)
                    acc[m2 * 4 + n] = fma2(av[m2], bp[n], acc[m2 * 4 + n]);
        }
    }
    const int colbase = bn * 64 + tx * 4;
#pragma unroll
    for (int m2 = 0; m2 < 4; ++m2) {
        int r0 = bm * 128 + ((m2 >= 2) ? 64 : 0) + ty * 4 + (m2 & 1) * 2;
        float2 p0 = unpackff(acc[m2 * 4 + 0]);
        float2 p1 = unpackff(acc[m2 * 4 + 1]);
        float2 p2 = unpackff(acc[m2 * 4 + 2]);
        float2 p3 = unpackff(acc[m2 * 4 + 3]);
        *(float4*)&g_h[r0 * HF + colbase] = make_float4(p0.x, p1.x, p2.x, p3.x);
        *(float4*)&g_h[(r0 + 1) * HF + colbase] = make_float4(p0.y, p1.y, p2.y, p3.y);
    }
}

// ---------------------------------------------------------------------------
// Kernel 2: e_src/e_dst (unchanged)
// ---------------------------------------------------------------------------
__global__ __launch_bounds__(256) void e_kernel(const float* __restrict__ a_src,
                                                const float* __restrict__ a_dst) {
    const int row = blockIdx.x;
    const int t = threadIdx.x;
    float v = g_h[row * HF + t];
    float s = v * a_src[t];
    float d = v * a_dst[t];
#pragma unroll
    for (int o = 16; o > 0; o >>= 1) {
        s += __shfl_down_sync(0xffffffffu, s, o);
        d += __shfl_down_sync(0xffffffffu, d, o);
    }
    __shared__ float ss[8], sd[8];
    const int w = t >> 5;
    if ((t & 31) == 0) { ss[w] = s; sd[w] = d; }
    __syncthreads();
    if (t < Hh) {
        g_es[row * Hh + t] = ss[2 * t] + ss[2 * t + 1];
        g_ed[row * Hh + t] = sd[2 * t] + sd[2 * t + 1];
    }
}

// ---------------------------------------------------------------------------
// Kernel 2b: pack B fragments.
// For jb (8 j's) / n-tile (8 f's): lane holds b0 = tf32(h[j0+lane%4][n8+lane/4]),
// b1 = tf32(h[j0+lane%4+4][n8+lane/4])  (m16n8k8 B col-major fragment layout).
// Grid (8, 64): CTA covers 128 j x 64 f of one bh.
// ---------------------------------------------------------------------------
__global__ __launch_bounds__(256) void pack_hT() {
    __shared__ float tsm[128][68];
    const int tid = threadIdx.x;
    const int jt = blockIdx.x;          // 0..7 (128 j each)
    const int bh = blockIdx.y;          // 0..63
    const int b = bh >> 2, h = bh & 3;
    const int j0 = jt << 7;

#pragma unroll
    for (int q = 0; q < 8; ++q) {
        int v = q * 256 + tid;          // 2048 float4
        int row = v >> 4, c4 = (v & 15) << 2;
        float4 x = *(const float4*)&g_h[(b * Nn + j0 + row) * HF + h * 64 + c4];
        tsm[row][c4 + 0] = x.x; tsm[row][c4 + 1] = x.y;
        tsm[row][c4 + 2] = x.z; tsm[row][c4 + 3] = x.w;
    }
    __syncthreads();

#pragma unroll
    for (int q = 0; q < 16; ++q) {
        int v = q * 256 + tid;          // 4096 uint2
        int jbl  = v >> 8;              // 0..15
        int n    = (v >> 5) & 7;
        int ln   = v & 31;
        int jl   = jbl * 8 + (ln & 3);
        int f    = n * 8 + (ln >> 2);
        uint2 o;
        o.x = cvt_tf32(tsm[jl][f]);
        o.y = cvt_tf32(tsm[jl + 4][f]);
        g_hTf[(size_t)((bh * 128 + jt * 16 + jbl) * 8 + n) * 32 + ln] = o;
    }
}

// ---------------------------------------------------------------------------
// Kernel 3: flash-GAT attention via mma.sync tf32.
// Grid (8 i-tiles, 64 bh), 256 thr = 8 warps; warp w owns i rows [16w,16w+16).
// j-tile = 64. Dynamic smem 52.5KB.
// ---------------------------------------------------------------------------
constexpr int OFF_ADJ = 0;                       // 128*68*4 = 34816
constexpr int OFF_HF  = 34816;                   // 64*32*8  = 16384
constexpr int OFF_ES  = 51200;                   // 256
constexpr int OFF_ED  = 51456;                   // 512
constexpr int OFF_DEN = 51968;                   // 512
constexpr int SMEM_ATTN = 52480;

__global__ __launch_bounds__(256) void attn_kernel(const float* __restrict__ adj,
                                                   const float* __restrict__ bias,
                                                   float* __restrict__ out) {
    extern __shared__ char dsm[];
    float (*adj_sm)[68] = (float(*)[68])(dsm + OFF_ADJ);
    uint2* hfrag  = (uint2*)(dsm + OFF_HF);      // [ks*8+n][lane]
    float* es_sm  = (float*)(dsm + OFF_ES);
    float* ed_sm  = (float*)(dsm + OFF_ED);
    float* den_sm = (float*)(dsm + OFF_DEN);

    const int tid = threadIdx.x;
    const int w = tid >> 5, lane = tid & 31;
    const int bh = blockIdx.y, b = bh >> 2, h = bh & 3;
    const int i0 = blockIdx.x << 7;
    const int i_w = w << 4;                      // warp's 16 local rows
    const int grp = lane >> 2;                   // 0..7 (fragment row group)
    const int tig = lane & 3;                    // 0..3 (thread in group)

    if (tid < 128) ed_sm[tid] = g_ed[(b * Nn + i0 + tid) * Hh + h];
    __syncthreads();
    const float ed0 = ed_sm[i_w + grp];
    const float ed1 = ed_sm[i_w + 8 + grp];

    float acc[8][4];
#pragma unroll
    for (int n = 0; n < 8; ++n)
#pragma unroll
        for (int k = 0; k < 4; ++k) acc[n][k] = 0.f;
    float den0 = 0.f, den1 = 0.f;

    for (int jt = 0; jt < 16; ++jt) {
        const int j0 = jt << 6;
        __syncthreads();                         // previous tile reads done

        // stage adj 128x64 (row pad 68)
#pragma unroll
        for (int q = 0; q < 8; ++q) {
            int v = (q << 8) + tid;
            int r = v >> 4, c4 = (v & 15) << 2;
            float4 av = *(const float4*)&adj[(size_t)(b * Nn + i0 + r) * Nn + j0 + c4];
            adj_sm[r][c4 + 0] = av.x; adj_sm[r][c4 + 1] = av.y;
            adj_sm[r][c4 + 2] = av.z; adj_sm[r][c4 + 3] = av.w;
        }
        // stage B fragments (straight copy, fragment order)
        {
            const uint4* hs = (const uint4*)(g_hTf + (size_t)(bh * 128 + jt * 8) * 8 * 32);
#pragma unroll
            for (int q = 0; q < 4; ++q)
                ((uint4*)hfrag)[(q << 8) + tid] = hs[(q << 8) + tid];
        }
        if (tid < 64) es_sm[tid] = g_es[(b * Nn + j0 + tid) * Hh + h];
        __syncthreads();

#pragma unroll
        for (int ks = 0; ks < 8; ++ks) {
            const int jj = (ks << 3) + tig;
            const float es0 = es_sm[jj];
            const float es1 = es_sm[jj + 4];

            float l00 = ed0 + es0; l00 = fmaxf(l00, 0.2f * l00);
            float l10 = ed1 + es0; l10 = fmaxf(l10, 0.2f * l10);
            float l01 = ed0 + es1; l01 = fmaxf(l01, 0.2f * l01);
            float l11 = ed1 + es1; l11 = fmaxf(l11, 0.2f * l11);
            float p00 = (adj_sm[i_w + grp][jj]      > 0.5f) ? __expf(l00) : 0.f;
            float p10 = (adj_sm[i_w + 8 + grp][jj]  > 0.5f) ? __expf(l10) : 0.f;
            float p01 = (adj_sm[i_w + grp][jj + 4]     > 0.5f) ? __expf(l01) : 0.f;
            float p11 = (adj_sm[i_w + 8 + grp][jj + 4] > 0.5f) ? __expf(l11) : 0.f;

            const u32 a0 = cvt_tf32(p00);        // (grp,   k=tig)
            const u32 a1 = cvt_tf32(p10);        // (grp+8, k=tig)
            const u32 a2 = cvt_tf32(p01);        // (grp,   k=tig+4)
            const u32 a3 = cvt_tf32(p11);        // (grp+8, k=tig+4)
            // denominator from the SAME rounded weights as the numerator
            den0 += __uint_as_float(a0) + __uint_as_float(a2);
            den1 += __uint_as_float(a1) + __uint_as_float(a3);

            const uint2* hrow = hfrag + (ks << 8) + lane;   // (ks*8+n)*32+lane
#pragma unroll
            for (int n = 0; n < 8; ++n) {
                uint2 bf = hrow[n << 5];
                mma16n8k8(acc[n], a0, a1, a2, a3, bf.x, bf.y);
            }
        }
    }

    // reduce den across the 4 lanes sharing each row
    den0 += __shfl_xor_sync(0xffffffffu, den0, 1);
    den0 += __shfl_xor_sync(0xffffffffu, den0, 2);
    den1 += __shfl_xor_sync(0xffffffffu, den1, 1);
    den1 += __shfl_xor_sync(0xffffffffu, den1, 2);
    if (tig == 0) {
        den_sm[i_w + grp] = den0;
        den_sm[i_w + 8 + grp] = den1;
    }
    __syncthreads();
    const float inv0 = 1.0f / den_sm[i_w + grp];
    const float inv1 = 1.0f / den_sm[i_w + 8 + grp];

    float* o0 = out + (size_t)(b * Nn + i0 + i_w + grp) * HF + h * 64;
    float* o1 = out + (size_t)(b * Nn + i0 + i_w + 8 + grp) * HF + h * 64;
#pragma unroll
    for (int n = 0; n < 8; ++n) {
        const int col = (n << 3) + (tig << 1);
        float2 bz = *(const float2*)&bias[h * 64 + col];
        float2 r0, r1;
        r0.x = acc[n][0] * inv0 + bz.x;  r0.y = acc[n][1] * inv0 + bz.y;
        r1.x = acc[n][2] * inv1 + bz.x;  r1.y = acc[n][3] * inv1 + bz.y;
        *(float2*)&o0[col] = r0;
        *(float2*)&o1[col] = r1;
    }
}

// ---------------------------------------------------------------------------
extern "C" void kernel_launch(void* const* d_in, const int* in_sizes, int n_in,
                              void* d_out, int out_size) {
    (void)in_sizes; (void)n_in; (void)out_size;
    const float* x     = (const float*)d_in[0];
    const float* adj   = (const float*)d_in[1];
    const float* W     = (const float*)d_in[2];
    const float* a_src = (const float*)d_in[3];
    const float* a_dst = (const float*)d_in[4];
    const float* bias  = (const float*)d_in[5];
    float* out = (float*)d_out;

    cudaFuncSetAttribute(attn_kernel,
                         cudaFuncAttributeMaxDynamicSharedMemorySize, SMEM_ATTN);

    gemm_xw<<<dim3(HF / 64, Mrows / 128), 256>>>(x, W);
    e_kernel<<<Mrows, 256>>>(a_src, a_dst);
    pack_hT<<<dim3(8, 64), 256>>>();
    attn_kernel<<<dim3(8, 64), 256, SMEM_ATTN>>>(adj, bias, out);
}

// round 7
// speedup vs baseline: 3.1677x; 1.3416x over previous
#include <cuda_runtime.h>
#include <cstdint>

// BatchedGAT round 6:
//   gemm_fused: h = x@W (fp32 f32x2 FMA) + fused epilogue that
//               (a) computes e_src/e_dst for its 128 rows x its head,
//               (b) emits tf32 B-fragments (m16n8k8 col-major) to g_hTf4.
//               g_h tensor eliminated.
//   attn: flash-GAT via mma.sync tf32 with cp.async 2-stage pipelined
//         staging of adj / fragments / e_src; exp via bare ex2 (log2e folded).

#define DEV __device__ __forceinline__
using u64 = unsigned long long;
using u32 = unsigned int;

DEV u64 packff(float lo, float hi) {
    u64 r; asm("mov.b64 %0, {%1,%2};" : "=l"(r) : "f"(lo), "f"(hi)); return r;
}
DEV u64 fma2(u64 a, u64 b, u64 c) {
    u64 r; asm("fma.rn.f32x2 %0, %1, %2, %3;" : "=l"(r) : "l"(a), "l"(b), "l"(c)); return r;
}
DEV float2 unpackff(u64 v) {
    float lo, hi; asm("mov.b64 {%0,%1}, %2;" : "=f"(lo), "=f"(hi) : "l"(v));
    return make_float2(lo, hi);
}
DEV u32 cvt_tf32(float x) {
    u32 r; asm("cvt.rna.tf32.f32 %0, %1;" : "=r"(r) : "f"(x)); return r;
}
DEV float ex2f(float x) {
    float r; asm("ex2.approx.f32 %0, %1;" : "=f"(r) : "f"(x)); return r;
}
DEV u32 smem_u32(const void* p) {
    u32 a; asm("{ .reg .u64 t; cvta.to.shared.u64 t, %1; cvt.u32.u64 %0, t; }"
               : "=r"(a) : "l"(p));
    return a;
}
DEV void cpasync16(u32 dst, const void* src) {
    asm volatile("cp.async.cg.shared.global [%0], [%1], 16;"
                 :: "r"(dst), "l"(src) : "memory");
}
#define CP_COMMIT() asm volatile("cp.async.commit_group;" ::: "memory")
#define CP_WAIT1()  asm volatile("cp.async.wait_group 1;" ::: "memory")
#define CP_WAIT0()  asm volatile("cp.async.wait_group 0;" ::: "memory")

DEV void mma16n8k8(float* c, u32 a0, u32 a1, u32 a2, u32 a3, u32 b0, u32 b1) {
    asm volatile(
        "mma.sync.aligned.m16n8k8.row.col.f32.tf32.tf32.f32 "
        "{%0,%1,%2,%3}, {%4,%5,%6,%7}, {%8,%9}, {%0,%1,%2,%3};"
        : "+f"(c[0]), "+f"(c[1]), "+f"(c[2]), "+f"(c[3])
        : "r"(a0), "r"(a1), "r"(a2), "r"(a3), "r"(b0), "r"(b1));
}

constexpr int Bb = 16, Nn = 1024, Dd = 256, Hh = 4, HF = 256;
constexpr int Mrows = Bb * Nn;
constexpr float LOG2E = 1.4426950408889634f;

// e arrays TRANSPOSED: [h][b*N + n]  (contiguous in n for cp.async)
__device__ float g_es[Hh * Mrows];
__device__ float g_ed[Hh * Mrows];
// B fragments: [bh][jb(128)][q(4)][lane(32)] uint4 = (n=2q:b0,b1, n=2q+1:b0,b1)
__device__ uint4 g_hTf4[64 * 128 * 4 * 32];   // 16.8 MB

// ---------------------------------------------------------------------------
// Kernel 1: gemm + fused e + fragment emission.
// Grid (4, 128): bn = head (64 cols), bm = 128-row block. 256 threads.
// ---------------------------------------------------------------------------
__global__ __launch_bounds__(256) void gemm_fused(const float* __restrict__ A,
                                                  const float* __restrict__ W,
                                                  const float* __restrict__ a_src,
                                                  const float* __restrict__ a_dst) {
    __shared__ float As[16][128];
    __shared__ float Bs[16][64];
    __shared__ float hs[128][68];     // h tile bounce for fragment emission

    const int tid = threadIdx.x;
    const int bm = blockIdx.y, bn = blockIdx.x;
    const int ty = tid >> 4, tx = tid & 15;

    u64 acc[16];
#pragma unroll
    for (int i = 0; i < 16; ++i) acc[i] = 0ull;

    const float* Ab = A + bm * 128 * Dd;
    const float* Wb = W + bn * 64;
    const int arow = tid >> 2, acol = (tid & 3) << 2;
    const int brow = tid >> 4, bcol = (tid & 15) << 2;

    for (int kt = 0; kt < Dd; kt += 16) {
        float4 a0 = *(const float4*)(Ab + arow * Dd + kt + acol);
        float4 a1 = *(const float4*)(Ab + (arow + 64) * Dd + kt + acol);
        float4 bv = *(const float4*)(Wb + (kt + brow) * HF + bcol);
        __syncthreads();
        As[acol + 0][arow] = a0.x; As[acol + 1][arow] = a0.y;
        As[acol + 2][arow] = a0.z; As[acol + 3][arow] = a0.w;
        As[acol + 0][arow + 64] = a1.x; As[acol + 1][arow + 64] = a1.y;
        As[acol + 2][arow + 64] = a1.z; As[acol + 3][arow + 64] = a1.w;
        *(float4*)&Bs[brow][bcol] = bv;
        __syncthreads();
#pragma unroll
        for (int kk = 0; kk < 16; ++kk) {
            ulonglong2 a01 = *(const ulonglong2*)&As[kk][ty * 4];
            ulonglong2 a23 = *(const ulonglong2*)&As[kk][64 + ty * 4];
            float4 b = *(const float4*)&Bs[kk][tx * 4];
            u64 av[4] = { a01.x, a01.y, a23.x, a23.y };
            u64 bp[4] = { packff(b.x, b.x), packff(b.y, b.y),
                          packff(b.z, b.z), packff(b.w, b.w) };
#pragma unroll
            for (int m2 = 0; m2 < 4; ++m2)
#pragma unroll
                for (int n = 0; n < 4; ++n)
                    acc[m2 * 4 + n] = fma2(av[m2], bp[n], acc[m2 * 4 + n]);
        }
    }

    // ---- epilogue: hs store + e partials ----
    const float4 as4 = *(const float4*)&a_src[bn * 64 + tx * 4];
    const float4 ad4 = *(const float4*)&a_dst[bn * 64 + tx * 4];
    float ps[8], pd[8];
#pragma unroll
    for (int r = 0; r < 8; ++r) { ps[r] = 0.f; pd[r] = 0.f; }

#pragma unroll
    for (int m2 = 0; m2 < 4; ++m2) {
        const int rloc = ((m2 >= 2) ? 64 : 0) + ty * 4 + (m2 & 1) * 2;
        float2 p0 = unpackff(acc[m2 * 4 + 0]);
        float2 p1 = unpackff(acc[m2 * 4 + 1]);
        float2 p2 = unpackff(acc[m2 * 4 + 2]);
        float2 p3 = unpackff(acc[m2 * 4 + 3]);
        hs[rloc][tx * 4 + 0] = p0.x;  hs[rloc + 1][tx * 4 + 0] = p0.y;
        hs[rloc][tx * 4 + 1] = p1.x;  hs[rloc + 1][tx * 4 + 1] = p1.y;
        hs[rloc][tx * 4 + 2] = p2.x;  hs[rloc + 1][tx * 4 + 2] = p2.y;
        hs[rloc][tx * 4 + 3] = p3.x;  hs[rloc + 1][tx * 4 + 3] = p3.y;
        ps[m2 * 2] = fmaf(p0.x, as4.x, fmaf(p1.x, as4.y,
                     fmaf(p2.x, as4.z, fmaf(p3.x, as4.w, ps[m2 * 2]))));
        ps[m2 * 2 + 1] = fmaf(p0.y, as4.x, fmaf(p1.y, as4.y,
                     fmaf(p2.y, as4.z, fmaf(p3.y, as4.w, ps[m2 * 2 + 1]))));
        pd[m2 * 2] = fmaf(p0.x, ad4.x, fmaf(p1.x, ad4.y,
                     fmaf(p2.x, ad4.z, fmaf(p3.x, ad4.w, pd[m2 * 2]))));
        pd[m2 * 2 + 1] = fmaf(p0.y, ad4.x, fmaf(p1.y, ad4.y,
                     fmaf(p2.y, ad4.z, fmaf(p3.y, ad4.w, pd[m2 * 2 + 1]))));
    }

    // reduce e over tx (lanes xor 1..8 stay within 16-lane half-warp)
#pragma unroll
    for (int r = 0; r < 8; ++r) {
#pragma unroll
        for (int o = 1; o < 16; o <<= 1) {
            ps[r] += __shfl_xor_sync(0xffffffffu, ps[r], o);
            pd[r] += __shfl_xor_sync(0xffffffffu, pd[r], o);
        }
    }
    if ((tid & 15) == 0) {
#pragma unroll
        for (int m2 = 0; m2 < 4; ++m2) {
            const int rloc = ((m2 >= 2) ? 64 : 0) + ty * 4 + (m2 & 1) * 2;
            const int rg = bm * 128 + rloc;
            g_es[bn * Mrows + rg]     = ps[m2 * 2];
            g_es[bn * Mrows + rg + 1] = ps[m2 * 2 + 1];
            g_ed[bn * Mrows + rg]     = pd[m2 * 2];
            g_ed[bn * Mrows + rg + 1] = pd[m2 * 2 + 1];
        }
    }
    __syncthreads();   // hs ready

    // ---- fragment emission: 2048 uint4 per CTA, 8 per thread ----
    const int b_ = bm >> 3;
    const int bh = b_ * 4 + bn;
    const int jb0 = (bm & 7) * 16;
#pragma unroll
    for (int q2 = 0; q2 < 8; ++q2) {
        int v = (q2 << 8) + tid;          // 0..2047
        int jbl = v >> 7;                 // 0..15
        int q = (v >> 5) & 3;             // 0..3
        int ln = v & 31;
        int jl = jbl * 8 + (ln & 3);
        int f0 = (2 * q) * 8 + (ln >> 2);
        uint4 o;
        o.x = cvt_tf32(hs[jl][f0]);
        o.y = cvt_tf32(hs[jl + 4][f0]);
        o.z = cvt_tf32(hs[jl][f0 + 8]);
        o.w = cvt_tf32(hs[jl + 4][f0 + 8]);
        g_hTf4[(size_t)((bh * 128 + jb0 + jbl) * 4 + q) * 32 + ln] = o;
    }
}

// ---------------------------------------------------------------------------
// Kernel 2: flash-GAT attention, cp.async 2-stage pipeline.
// Grid (8 i-tiles, 64 bh), 256 thr; warp w owns i rows [16w,16w+16).
// ---------------------------------------------------------------------------
constexpr int ADJ_ST = 68;
constexpr int OFF_ADJ0 = 0;                    // 128*68*4 = 34816
constexpr int OFF_ADJ1 = 34816;
constexpr int OFF_HF0  = 69632;                // 16384
constexpr int OFF_HF1  = 86016;
constexpr int OFF_ES0  = 102400;               // 256
constexpr int OFF_ES1  = 102656;
constexpr int OFF_ED   = 102912;               // 512
constexpr int OFF_DEN  = 103424;               // 512
constexpr int SMEM_ATTN = 103936;

__global__ __launch_bounds__(256, 2) void attn_kernel(const float* __restrict__ adj,
                                                      const float* __restrict__ bias,
                                                      float* __restrict__ out) {
    extern __shared__ char dsm[];
    const u32 sbase = smem_u32(dsm);
    float* ed_sm  = (float*)(dsm + OFF_ED);
    float* den_sm = (float*)(dsm + OFF_DEN);

    const int tid = threadIdx.x;
    const int w = tid >> 5, lane = tid & 31;
    const int bh = blockIdx.y, b = bh >> 2, h = bh & 3;
    const int i0 = blockIdx.x << 7;
    const int i_w = w << 4;
    const int grp = lane >> 2;
    const int tig = lane & 3;

    const u32 adj_off[2] = { sbase + OFF_ADJ0, sbase + OFF_ADJ1 };
    const u32 hf_off[2]  = { sbase + OFF_HF0,  sbase + OFF_HF1 };
    const u32 es_off[2]  = { sbase + OFF_ES0,  sbase + OFF_ES1 };

    const float* adj_base = adj + (size_t)(b * Nn + i0) * Nn;
    const uint4* hf_base = g_hTf4 + (size_t)bh * 128 * 4 * 32;
    const float* es_base = g_es + h * Mrows + b * Nn;

    // ---- staging lambda (cp.async) ----
    auto stage = [&](int jt, int sel) {
        const int j0 = jt << 6;
        const int r = tid >> 4, c4 = (tid & 15) << 2;
#pragma unroll
        for (int q = 0; q < 8; ++q)
            cpasync16(adj_off[sel] + (u32)(((q << 4) + r) * ADJ_ST + c4) * 4u,
                      adj_base + (size_t)((q << 4) + r) * Nn + j0 + c4);
        const uint4* hs = hf_base + (size_t)(jt * 8) * 4 * 32;
#pragma unroll
        for (int q = 0; q < 4; ++q)
            cpasync16(hf_off[sel] + (u32)((q << 8) + tid) * 16u, hs + (q << 8) + tid);
        if (tid < 16)
            cpasync16(es_off[sel] + (u32)tid * 16u, es_base + j0 + tid * 4);
    };

    stage(0, 0); CP_COMMIT();
    if (tid < 128) ed_sm[tid] = g_ed[h * Mrows + b * Nn + i0 + tid] * LOG2E;

    float acc[8][4];
#pragma unroll
    for (int n = 0; n < 8; ++n)
#pragma unroll
        for (int k = 0; k < 4; ++k) acc[n][k] = 0.f;
    float den0 = 0.f, den1 = 0.f;

    __syncthreads();   // ed_sm ready
    const float ed0 = ed_sm[i_w + grp];
    const float ed1 = ed_sm[i_w + 8 + grp];

    for (int jt = 0; jt < 16; ++jt) {
        const int sel = jt & 1;
        if (jt < 15) { stage(jt + 1, sel ^ 1); CP_COMMIT(); }
        if (jt < 15) CP_WAIT1(); else CP_WAIT0();
        __syncthreads();   // stage(jt) visible to all

        const float* adj_sm = (const float*)(dsm + (sel ? OFF_ADJ1 : OFF_ADJ0));
        const uint4* hfrag  = (const uint4*)(dsm + (sel ? OFF_HF1 : OFF_HF0));
        const float* es_sm  = (const float*)(dsm + (sel ? OFF_ES1 : OFF_ES0));

#pragma unroll
        for (int ks = 0; ks < 8; ++ks) {
            const int jj = (ks << 3) + tig;
            const float es0 = es_sm[jj];
            const float es1 = es_sm[jj + 4];

            float l00 = fmaf(es0, LOG2E, ed0); l00 = fmaxf(l00, 0.2f * l00);
            float l10 = fmaf(es0, LOG2E, ed1); l10 = fmaxf(l10, 0.2f * l10);
            float l01 = fmaf(es1, LOG2E, ed0); l01 = fmaxf(l01, 0.2f * l01);
            float l11 = fmaf(es1, LOG2E, ed1); l11 = fmaxf(l11, 0.2f * l11);
            float p00 = (adj_sm[(i_w + grp) * ADJ_ST + jj]          > 0.5f) ? ex2f(l00) : 0.f;
            float p10 = (adj_sm[(i_w + 8 + grp) * ADJ_ST + jj]      > 0.5f) ? ex2f(l10) : 0.f;
            float p01 = (adj_sm[(i_w + grp) * ADJ_ST + jj + 4]      > 0.5f) ? ex2f(l01) : 0.f;
            float p11 = (adj_sm[(i_w + 8 + grp) * ADJ_ST + jj + 4]  > 0.5f) ? ex2f(l11) : 0.f;

            const u32 a0 = cvt_tf32(p00);
            const u32 a1 = cvt_tf32(p10);
            const u32 a2 = cvt_tf32(p01);
            const u32 a3 = cvt_tf32(p11);
            den0 += __uint_as_float(a0) + __uint_as_float(a2);
            den1 += __uint_as_float(a1) + __uint_as_float(a3);

            const uint4* hrow = hfrag + (ks << 7) + lane;    // (ks*4+q)*32+lane
#pragma unroll
            for (int q = 0; q < 4; ++q) {
                uint4 bf = hrow[q << 5];
                mma16n8k8(acc[2 * q],     a0, a1, a2, a3, bf.x, bf.y);
                mma16n8k8(acc[2 * q + 1], a0, a1, a2, a3, bf.z, bf.w);
            }
        }
        __syncthreads();   // all reads of buf[sel] done before restage
    }

    den0 += __shfl_xor_sync(0xffffffffu, den0, 1);
    den0 += __shfl_xor_sync(0xffffffffu, den0, 2);
    den1 += __shfl_xor_sync(0xffffffffu, den1, 1);
    den1 += __shfl_xor_sync(0xffffffffu, den1, 2);
    if (tig == 0) {
        den_sm[i_w + grp] = den0;
        den_sm[i_w + 8 + grp] = den1;
    }
    __syncthreads();
    const float inv0 = 1.0f / den_sm[i_w + grp];
    const float inv1 = 1.0f / den_sm[i_w + 8 + grp];

    float* o0 = out + (size_t)(b * Nn + i0 + i_w + grp) * HF + h * 64;
    float* o1 = out + (size_t)(b * Nn + i0 + i_w + 8 + grp) * HF + h * 64;
#pragma unroll
    for (int n = 0; n < 8; ++n) {
        const int col = (n << 3) + (tig << 1);
        float2 bz = *(const float2*)&bias[h * 64 + col];
        float2 r0, r1;
        r0.x = acc[n][0] * inv0 + bz.x;  r0.y = acc[n][1] * inv0 + bz.y;
        r1.x = acc[n][2] * inv1 + bz.x;  r1.y = acc[n][3] * inv1 + bz.y;
        *(float2*)&o0[col] = r0;
        *(float2*)&o1[col] = r1;
    }
}

// ---------------------------------------------------------------------------
extern "C" void kernel_launch(void* const* d_in, const int* in_sizes, int n_in,
                              void* d_out, int out_size) {
    (void)in_sizes; (void)n_in; (void)out_size;
    const float* x     = (const float*)d_in[0];
    const float* adj   = (const float*)d_in[1];
    const float* W     = (const float*)d_in[2];
    const float* a_src = (const float*)d_in[3];
    const float* a_dst = (const float*)d_in[4];
    const float* bias  = (const float*)d_in[5];
    float* out = (float*)d_out;

    cudaFuncSetAttribute(attn_kernel,
                         cudaFuncAttributeMaxDynamicSharedMemorySize, SMEM_ATTN);

    gemm_fused<<<dim3(HF / 64, Mrows / 128), 256>>>(x, W, a_src, a_dst);
    attn_kernel<<<dim3(8, 64), 256, SMEM_ATTN>>>(adj, bias, out);
}